// round 1
// baseline (speedup 1.0000x reference)
#include <cuda_runtime.h>

// SSIM loss: 5 depthwise 11x11 gaussian blurs (separable) + pointwise SSIM + global mean.
// B=16, C=3, H=W=512. Planes = 48. Tile 32x32 per block, halo 5 each side.

#define TW 32
#define TH 32
#define HALO 5
#define SH 42   // TH + 2*HALO
#define SW 42   // TW + 2*HALO
#define SWP 43  // padded row stride (floats) for input stats: 43 % 32 = 11 (coprime) -> conflict-free
#define HWP 33  // padded row stride for horizontally-blurred stats: 33 % 32 = 1 -> conflict-free
#define IMG 512
#define NPLANES 48

// Gaussian window, sigma=1.5, normalized (computed in double, ~2e-7 accurate)
__device__ constexpr float GW[11] = {
    0.00102838f, 0.00759877f, 0.03600077f, 0.10936079f, 0.21300554f,
    0.26601173f,
    0.21300554f, 0.10936079f, 0.03600077f, 0.00759877f, 0.00102838f};

#define SSIM_C1 0.0001f
#define SSIM_C2 0.0009f
#define INV_N (1.0f / (16.0f * 3.0f * 512.0f * 512.0f))

#define SMEM_FLOATS (5 * SH * SWP + 5 * SH * HWP + 8)
#define SMEM_BYTES (SMEM_FLOATS * 4)

__global__ void zero_out_kernel(float* out) { out[0] = 0.0f; }

__global__ __launch_bounds__(256, 1)
void ssim_kernel(const float* __restrict__ input, const float* __restrict__ target,
                 float* __restrict__ out) {
    extern __shared__ float smem[];
    float* sS = smem;                  // [5][SH][SWP]  t, i, t*t, i*i, t*i
    float* sH = smem + 5 * SH * SWP;   // [5][SH][HWP]  horizontally blurred stats
    float* red = sH + 5 * SH * HWP;    // [8] block-reduce scratch

    const int tid = threadIdx.x;
    const int plane = blockIdx.z;  // 0..47  (b*3 + c)
    const float* Tp = target + (size_t)plane * (IMG * IMG);
    const float* Ip = input + (size_t)plane * (IMG * IMG);
    const int gx0 = blockIdx.x * TW - HALO;
    const int gy0 = blockIdx.y * TH - HALO;

    // ---- Phase 1: load tile (+halo) and compute products into smem ----
    for (int idx = tid; idx < SH * SW; idx += 256) {
        int r = idx / SW;
        int c = idx - r * SW;
        int gx = gx0 + c;
        int gy = gy0 + r;
        float t = 0.0f, v = 0.0f;
        if ((unsigned)gx < (unsigned)IMG && (unsigned)gy < (unsigned)IMG) {
            t = Tp[gy * IMG + gx];
            v = Ip[gy * IMG + gx];
        }
        int o = r * SWP + c;
        sS[0 * SH * SWP + o] = t;
        sS[1 * SH * SWP + o] = v;
        sS[2 * SH * SWP + o] = t * t;
        sS[3 * SH * SWP + o] = v * v;
        sS[4 * SH * SWP + o] = t * v;
    }
    __syncthreads();

    // ---- Phase 2: horizontal blur. 5 stats x 42 rows = 210 tasks, one per thread.
    // Sliding-window register blocking: 42 LDS -> 352 imm-FFMA -> 32 outputs per task.
    if (tid < 5 * SH) {
        int stat = tid / SH;
        int row = tid - stat * SH;
        const float* src = sS + (stat * SH + row) * SWP;
        float acc[TW];
#pragma unroll
        for (int r = 0; r < TW; r++) acc[r] = 0.0f;
#pragma unroll
        for (int j = 0; j < SW; j++) {
            float v = src[j];
#pragma unroll
            for (int r = 0; r < TW; r++) {
                if (j - r >= 0 && j - r < 11) acc[r] = fmaf(v, GW[j - r], acc[r]);
            }
        }
        float* dst = sH + (stat * SH + row) * HWP;
#pragma unroll
        for (int r = 0; r < TW; r++) dst[r] = acc[r];
    }
    __syncthreads();

    // ---- Phase 3: vertical blur (4 output rows per thread) + SSIM + reduce ----
    const int tx = tid & 31;
    const int ty = tid >> 5;  // 0..7, each covers rows [4*ty, 4*ty+4)
    float st[5][4];
#pragma unroll
    for (int s = 0; s < 5; s++) {
        float a0 = 0.0f, a1 = 0.0f, a2 = 0.0f, a3 = 0.0f;
        const float* col = sH + (s * SH + ty * 4) * HWP + tx;
#pragma unroll
        for (int j = 0; j < 14; j++) {
            float v = col[j * HWP];
            if (j < 11) a0 = fmaf(v, GW[j], a0);
            if (j >= 1 && j < 12) a1 = fmaf(v, GW[j - 1], a1);
            if (j >= 2 && j < 13) a2 = fmaf(v, GW[j - 2], a2);
            if (j >= 3) a3 = fmaf(v, GW[j - 3], a3);
        }
        st[s][0] = a0;
        st[s][1] = a1;
        st[s][2] = a2;
        st[s][3] = a3;
    }

    float acc = 0.0f;
#pragma unroll
    for (int r = 0; r < 4; r++) {
        float mu1 = st[0][r], mu2 = st[1][r];
        float e11 = st[2][r], e22 = st[3][r], e12 = st[4][r];
        float mu1s = mu1 * mu1;
        float mu2s = mu2 * mu2;
        float mu12 = mu1 * mu2;
        float s1 = e11 - mu1s;
        float s2 = e22 - mu2s;
        float s12 = e12 - mu12;
        float num = (2.0f * mu12 + SSIM_C1) * (2.0f * s12 + SSIM_C2);
        float den = (mu1s + mu2s + SSIM_C1) * (s1 + s2 + SSIM_C2);
        float ssim = __fdividef(num, den);
        // mask: center target pixel > 0
        float tc = sS[0 * SH * SWP + (HALO + ty * 4 + r) * SWP + (HALO + tx)];
        acc += (tc > 0.0f) ? (1.0f - ssim) : 0.0f;
    }

    // warp reduce
#pragma unroll
    for (int off = 16; off; off >>= 1) acc += __shfl_xor_sync(0xFFFFFFFFu, acc, off);
    if (tx == 0) red[ty] = acc;
    __syncthreads();
    if (tid == 0) {
        float s = 0.0f;
#pragma unroll
        for (int w = 0; w < 8; w++) s += red[w];
        atomicAdd(out, s * INV_N);
    }
}

extern "C" void kernel_launch(void* const* d_in, const int* in_sizes, int n_in,
                              void* d_out, int out_size) {
    const float* input = (const float*)d_in[0];
    const float* target = (const float*)d_in[1];
    float* out = (float*)d_out;

    cudaFuncSetAttribute(ssim_kernel, cudaFuncAttributeMaxDynamicSharedMemorySize, SMEM_BYTES);

    zero_out_kernel<<<1, 1>>>(out);
    dim3 grid(IMG / TW, IMG / TH, NPLANES);  // 16 x 16 x 48
    ssim_kernel<<<grid, 256, SMEM_BYTES>>>(input, target, out);
}

// round 2
// speedup vs baseline: 1.1515x; 1.1515x over previous
#include <cuda_runtime.h>

// SSIM loss: 5 depthwise 11x11 gaussian blurs (separable) + pointwise SSIM + global mean.
// B=16, C=3, H=W=512. Planes = 48. Tile 32x32 per block, halo 5 each side.
//
// Round 2: latency-bound fix. Store only raw t,i in smem (products computed on the fly
// in the horizontal pass via uniform A*B with a ones-row), vectorized conflict-free
// LDS.128/STS.128 (strides 44 / 36), smem 63.8KB -> 45.2KB for 4 blocks/SM.

#define TW 32
#define TH 32
#define HALO 5
#define SH 42   // TH + 2*HALO
#define SW 42   // TW + 2*HALO
#define SWP 44  // padded stride for raw t/i rows: 16B-aligned, 44%32=12 -> LDS.128 conflict-free
#define HWP 36  // padded stride for h-blurred rows: 16B-aligned, 36%32=4 -> conflict-free
#define IMG 512
#define NPLANES 48

// Gaussian window, sigma=1.5, normalized (computed in double, ~2e-7 accurate)
__device__ constexpr float GW[11] = {
    0.00102838f, 0.00759877f, 0.03600077f, 0.10936079f, 0.21300554f,
    0.26601173f,
    0.21300554f, 0.10936079f, 0.03600077f, 0.00759877f, 0.00102838f};

#define SSIM_C1 0.0001f
#define SSIM_C2 0.0009f
#define INV_N (1.0f / (16.0f * 3.0f * 512.0f * 512.0f))

// smem layout (floats): sT[42*44] | sI[42*44] | ones[44] | sH[5*42*36] | red[8]
#define OFF_T 0
#define OFF_I (SH * SWP)
#define OFF_ONES (2 * SH * SWP)
#define OFF_H (OFF_ONES + SWP)
#define OFF_RED (OFF_H + 5 * SH * HWP)
#define SMEM_FLOATS (OFF_RED + 8)
#define SMEM_BYTES (SMEM_FLOATS * 4)

__global__ void zero_out_kernel(float* out) { out[0] = 0.0f; }

__global__ __launch_bounds__(256, 4)
void ssim_kernel(const float* __restrict__ input, const float* __restrict__ target,
                 float* __restrict__ out) {
    extern __shared__ float smem[];
    float* sT = smem + OFF_T;
    float* sI = smem + OFF_I;
    float* sOnes = smem + OFF_ONES;
    float* sH = smem + OFF_H;
    float* red = smem + OFF_RED;

    const int tid = threadIdx.x;
    const int plane = blockIdx.z;  // 0..47
    const float* Tp = target + (size_t)plane * (IMG * IMG);
    const float* Ip = input + (size_t)plane * (IMG * IMG);
    const int gx0 = blockIdx.x * TW - HALO;
    const int gy0 = blockIdx.y * TH - HALO;

    // ---- Phase 1: load tile (+halo) raw t, i into smem ----
    for (int idx = tid; idx < SH * SW; idx += 256) {
        int r = idx / SW;
        int c = idx - r * SW;
        int gx = gx0 + c;
        int gy = gy0 + r;
        float t = 0.0f, v = 0.0f;
        if ((unsigned)gx < (unsigned)IMG && (unsigned)gy < (unsigned)IMG) {
            t = Tp[gy * IMG + gx];
            v = Ip[gy * IMG + gx];
        }
        sT[r * SWP + c] = t;
        sI[r * SWP + c] = v;
    }
    if (tid < SWP) sOnes[tid] = 1.0f;
    __syncthreads();

    // ---- Phase 2: horizontal blur of 5 stats, products on the fly.
    // Task = (stat, row): v[j] = A[j]*B[j], sliding-window 32 outputs, imm-FFMA.
    //   stat 0: t*1   stat 1: i*1   stat 2: t*t   stat 3: i*i   stat 4: t*i
    if (tid < 5 * SH) {
        int stat = tid / SH;
        int row = tid - stat * SH;
        const float* tRow = sT + row * SWP;
        const float* iRow = sI + row * SWP;
        const float* A = (stat == 1 || stat == 3) ? iRow : tRow;
        const float* B = (stat < 2) ? sOnes : ((stat == 2) ? tRow : iRow);

        float acc[TW];
#pragma unroll
        for (int r = 0; r < TW; r++) acc[r] = 0.0f;

        const float4* A4 = (const float4*)A;
        const float4* B4 = (const float4*)B;
#pragma unroll
        for (int q = 0; q < 10; q++) {
            float4 av = A4[q];
            float4 bv = B4[q];
            float v[4] = {av.x * bv.x, av.y * bv.y, av.z * bv.z, av.w * bv.w};
#pragma unroll
            for (int e = 0; e < 4; e++) {
                int j = q * 4 + e;
#pragma unroll
                for (int r = 0; r < TW; r++) {
                    if (j - r >= 0 && j - r < 11) acc[r] = fmaf(v[e], GW[j - r], acc[r]);
                }
            }
        }
        {
            float2 a2 = ((const float2*)A)[20];
            float2 b2 = ((const float2*)B)[20];
            float v0 = a2.x * b2.x, v1 = a2.y * b2.y;
#pragma unroll
            for (int r = 0; r < TW; r++) {
                if (40 - r >= 0 && 40 - r < 11) acc[r] = fmaf(v0, GW[40 - r], acc[r]);
                if (41 - r >= 0 && 41 - r < 11) acc[r] = fmaf(v1, GW[41 - r], acc[r]);
            }
        }
        float4* D4 = (float4*)(sH + (stat * SH + row) * HWP);
#pragma unroll
        for (int q = 0; q < 8; q++)
            D4[q] = make_float4(acc[4 * q], acc[4 * q + 1], acc[4 * q + 2], acc[4 * q + 3]);
    }
    __syncthreads();

    // ---- Phase 3: vertical blur (4 output rows per thread) + SSIM + reduce ----
    const int tx = tid & 31;
    const int ty = tid >> 5;  // 0..7, rows [4*ty, 4*ty+4)
    float st[5][4];
#pragma unroll
    for (int s = 0; s < 5; s++) {
        float a0 = 0.0f, a1 = 0.0f, a2 = 0.0f, a3 = 0.0f;
        const float* col = sH + (s * SH + ty * 4) * HWP + tx;
#pragma unroll
        for (int j = 0; j < 14; j++) {
            float v = col[j * HWP];
            if (j < 11) a0 = fmaf(v, GW[j], a0);
            if (j >= 1 && j < 12) a1 = fmaf(v, GW[j - 1], a1);
            if (j >= 2 && j < 13) a2 = fmaf(v, GW[j - 2], a2);
            if (j >= 3) a3 = fmaf(v, GW[j - 3], a3);
        }
        st[s][0] = a0;
        st[s][1] = a1;
        st[s][2] = a2;
        st[s][3] = a3;
    }

    float acc = 0.0f;
#pragma unroll
    for (int r = 0; r < 4; r++) {
        float mu1 = st[0][r], mu2 = st[1][r];
        float e11 = st[2][r], e22 = st[3][r], e12 = st[4][r];
        float mu1s = mu1 * mu1;
        float mu2s = mu2 * mu2;
        float mu12 = mu1 * mu2;
        float s1 = e11 - mu1s;
        float s2 = e22 - mu2s;
        float s12 = e12 - mu12;
        float num = (2.0f * mu12 + SSIM_C1) * (2.0f * s12 + SSIM_C2);
        float den = (mu1s + mu2s + SSIM_C1) * (s1 + s2 + SSIM_C2);
        float ssim = __fdividef(num, den);
        float tc = sT[(HALO + ty * 4 + r) * SWP + (HALO + tx)];
        acc += (tc > 0.0f) ? (1.0f - ssim) : 0.0f;
    }

    // warp reduce
#pragma unroll
    for (int off = 16; off; off >>= 1) acc += __shfl_xor_sync(0xFFFFFFFFu, acc, off);
    if (tx == 0) red[ty] = acc;
    __syncthreads();
    if (tid == 0) {
        float s = 0.0f;
#pragma unroll
        for (int w = 0; w < 8; w++) s += red[w];
        atomicAdd(out, s * INV_N);
    }
}

extern "C" void kernel_launch(void* const* d_in, const int* in_sizes, int n_in,
                              void* d_out, int out_size) {
    const float* input = (const float*)d_in[0];
    const float* target = (const float*)d_in[1];
    float* out = (float*)d_out;

    cudaFuncSetAttribute(ssim_kernel, cudaFuncAttributeMaxDynamicSharedMemorySize, SMEM_BYTES);

    zero_out_kernel<<<1, 1>>>(out);
    dim3 grid(IMG / TW, IMG / TH, NPLANES);  // 16 x 16 x 48
    ssim_kernel<<<grid, 256, SMEM_BYTES>>>(input, target, out);
}

// round 3
// speedup vs baseline: 1.3263x; 1.1518x over previous
#include <cuda_runtime.h>

// SSIM loss: depthwise 11x11 gaussian (separable) + pointwise SSIM + global mean.
// B=16, C=3, H=W=512. Planes = 48. Tile 32x32 per block, halo 5 each side.
//
// Round 3: 4 stats (t, i, t^2+i^2, t*i) instead of 5; pure-blur phase 2 reading
// precomputed product planes; transposed h-blur output so phase 3 uses vector LDS.
// All smem access patterns bank-conflict-free by construction.

#define TW 32
#define TH 32
#define HALO 5
#define SH 42     // TH + 2*HALO
#define SW 42     // TW + 2*HALO
#define SWP 44    // padded input-plane row stride (16B aligned)
#define PLANE 1848  // SH * SWP, input plane size; 1848%32=24 -> interleaved LDS.128 conflict-free
#define CT 44     // sHT column stride (floats): 3*tx mod 8 distinct -> LDS.128 conflict-free
#define PT 1416   // sHT plane stride: 32*44 + 8 -> 8*stat bank offset -> scalar STS conflict-free
#define IMG 512
#define NPLANES 48

// Gaussian window, sigma=1.5, normalized (computed in double, ~2e-7 accurate)
__device__ constexpr float GW[11] = {
    0.00102838f, 0.00759877f, 0.03600077f, 0.10936079f, 0.21300554f,
    0.26601173f,
    0.21300554f, 0.10936079f, 0.03600077f, 0.00759877f, 0.00102838f};

#define SSIM_C1 0.0001f
#define SSIM_C2 0.0009f
#define INV_N (1.0f / (16.0f * 3.0f * 512.0f * 512.0f))

// smem layout (floats): 4 input planes | 4 transposed h-blur planes | red[8]
#define OFF_H (4 * PLANE)
#define OFF_RED (OFF_H + 4 * PT)
#define SMEM_FLOATS (OFF_RED + 8)
#define SMEM_BYTES (SMEM_FLOATS * 4)

__global__ void zero_out_kernel(float* out) { out[0] = 0.0f; }

__global__ __launch_bounds__(256, 4)
void ssim_kernel(const float* __restrict__ input, const float* __restrict__ target,
                 float* __restrict__ out) {
    extern __shared__ float smem[];
    float* sHT = smem + OFF_H;
    float* red = smem + OFF_RED;

    const int tid = threadIdx.x;
    const int plane = blockIdx.z;  // 0..47
    const float* Tp = target + (size_t)plane * (IMG * IMG);
    const float* Ip = input + (size_t)plane * (IMG * IMG);
    const int gx0 = blockIdx.x * TW - HALO;
    const int gy0 = blockIdx.y * TH - HALO;

    // ---- Phase 1: load tile (+halo); store planes t, i, q=t^2+i^2, r=t*i ----
    for (int idx = tid; idx < SH * SW; idx += 256) {
        int r = idx / SW;
        int c = idx - r * SW;
        int gx = gx0 + c;
        int gy = gy0 + r;
        float t = 0.0f, v = 0.0f;
        if ((unsigned)gx < (unsigned)IMG && (unsigned)gy < (unsigned)IMG) {
            t = Tp[gy * IMG + gx];
            v = Ip[gy * IMG + gx];
        }
        int o = r * SWP + c;
        smem[0 * PLANE + o] = t;
        smem[1 * PLANE + o] = v;
        smem[2 * PLANE + o] = fmaf(t, t, v * v);
        smem[3 * PLANE + o] = t * v;
    }
    __syncthreads();

    // ---- Phase 2: horizontal blur. Task = (stat, row), stat-minor interleave.
    // Pure sliding-window blur of one smem row: 11 vec LDS -> 352 imm-FFMA -> 32 outputs,
    // written TRANSPOSED into sHT[stat][col][row].
    if (tid < 4 * SH) {
        const int stat = tid & 3;
        const int row = tid >> 2;
        const float* src = smem + stat * PLANE + row * SWP;

        float acc[TW];
#pragma unroll
        for (int r = 0; r < TW; r++) acc[r] = 0.0f;

        const float4* A4 = (const float4*)src;
#pragma unroll
        for (int q = 0; q < 10; q++) {
            float4 av = A4[q];
            float v[4] = {av.x, av.y, av.z, av.w};
#pragma unroll
            for (int e = 0; e < 4; e++) {
                int j = q * 4 + e;
#pragma unroll
                for (int r = 0; r < TW; r++) {
                    if (j - r >= 0 && j - r < 11) acc[r] = fmaf(v[e], GW[j - r], acc[r]);
                }
            }
        }
        {
            float2 a2 = ((const float2*)src)[20];
#pragma unroll
            for (int r = 0; r < TW; r++) {
                if (40 - r >= 0 && 40 - r < 11) acc[r] = fmaf(a2.x, GW[40 - r], acc[r]);
                if (41 - r >= 0 && 41 - r < 11) acc[r] = fmaf(a2.y, GW[41 - r], acc[r]);
            }
        }
        // Transposed store: bank = (8*stat + drow + uniform) mod 32 -> 32 distinct banks.
        float* dst = sHT + stat * PT + row;
#pragma unroll
        for (int r = 0; r < TW; r++) dst[r * CT] = acc[r];
    }
    __syncthreads();

    // ---- Phase 3: vertical blur (4 output rows/thread) + SSIM + reduce ----
    const int tx = tid & 31;
    const int ty = tid >> 5;  // 0..7, rows [4*ty, 4*ty+4)
    float st[4][4];
#pragma unroll
    for (int s = 0; s < 4; s++) {
        // 14 consecutive rows of column tx: 3x LDS.128 + 1x LDS.64, conflict-free.
        const float* col = sHT + s * PT + tx * CT + 4 * ty;
        float f[14];
        float4 v0 = *(const float4*)(col);
        float4 v1 = *(const float4*)(col + 4);
        float4 v2 = *(const float4*)(col + 8);
        float2 v3 = *(const float2*)(col + 12);
        f[0] = v0.x; f[1] = v0.y; f[2] = v0.z; f[3] = v0.w;
        f[4] = v1.x; f[5] = v1.y; f[6] = v1.z; f[7] = v1.w;
        f[8] = v2.x; f[9] = v2.y; f[10] = v2.z; f[11] = v2.w;
        f[12] = v3.x; f[13] = v3.y;
#pragma unroll
        for (int r = 0; r < 4; r++) {
            float a = 0.0f;
#pragma unroll
            for (int k = 0; k < 11; k++) a = fmaf(f[r + k], GW[k], a);
            st[s][r] = a;
        }
    }

    float acc = 0.0f;
#pragma unroll
    for (int r = 0; r < 4; r++) {
        float mu1 = st[0][r], mu2 = st[1][r];
        float eq = st[2][r], e12 = st[3][r];
        float mu1s = mu1 * mu1;
        float mu2s = mu2 * mu2;
        float mu12 = mu1 * mu2;
        float musum = mu1s + mu2s;
        float ssum = eq - musum;          // sigma1^2 + sigma2^2
        float s12 = e12 - mu12;
        float num = (2.0f * mu12 + SSIM_C1) * (2.0f * s12 + SSIM_C2);
        float den = (musum + SSIM_C1) * (ssum + SSIM_C2);
        float ssim = __fdividef(num, den);
        float tc = smem[(HALO + ty * 4 + r) * SWP + (HALO + tx)];  // t plane
        acc += (tc > 0.0f) ? (1.0f - ssim) : 0.0f;
    }

    // warp reduce + block reduce + global atomic
#pragma unroll
    for (int off = 16; off; off >>= 1) acc += __shfl_xor_sync(0xFFFFFFFFu, acc, off);
    if (tx == 0) red[ty] = acc;
    __syncthreads();
    if (tid == 0) {
        float s = 0.0f;
#pragma unroll
        for (int w = 0; w < 8; w++) s += red[w];
        atomicAdd(out, s * INV_N);
    }
}

extern "C" void kernel_launch(void* const* d_in, const int* in_sizes, int n_in,
                              void* d_out, int out_size) {
    const float* input = (const float*)d_in[0];
    const float* target = (const float*)d_in[1];
    float* out = (float*)d_out;

    cudaFuncSetAttribute(ssim_kernel, cudaFuncAttributeMaxDynamicSharedMemorySize, SMEM_BYTES);

    zero_out_kernel<<<1, 1>>>(out);
    dim3 grid(IMG / TW, IMG / TH, NPLANES);  // 16 x 16 x 48
    ssim_kernel<<<grid, 256, SMEM_BYTES>>>(input, target, out);
}

// round 4
// speedup vs baseline: 1.3455x; 1.0145x over previous
#include <cuda_runtime.h>

// SSIM loss: depthwise 11x11 gaussian (separable) + pointwise SSIM + global mean.
// B=16, C=3, H=W=512. Planes = 48. Tile 32x32 per block, halo 5 each side.
//
// Round 4: f32x2 (FFMA2) packing. Stats processed as two lane-packed pairs:
//   pair 0 = (t, i) -> (mu1, mu2);  pair 1 = (t^2+i^2, t*i) -> (Eq, E12).
// Pairs stored interleaved in smem so ld.shared.v2.u64 yields packed operands.
// Coefficients are 64-bit broadcast constants. Halves FMA/LDS/STS issue count.

typedef unsigned long long u64;

#define TW 32
#define TH 32
#define HALO 5
#define SH 42
#define SW 42
#define IMG 512
#define NPLANES 48

#define RS 92            // input pair-plane row stride in floats (46 pairs): quad step 23%8=7 -> conflict-free
#define PP 3864          // SH * RS, input pair-plane size (floats)
#define CS 92            // sHT column stride in floats (46 row-pairs)
#define PT 2944          // 32 * CS, sHT pair-plane size (floats)

#define OFF_HT (2 * PP)           // 7728
#define OFF_RED (OFF_HT + 2 * PT) // 13616
#define SMEM_FLOATS (OFF_RED + 8)
#define SMEM_BYTES (SMEM_FLOATS * 4)

__device__ constexpr float GW[11] = {
    0.00102838f, 0.00759877f, 0.03600077f, 0.10936079f, 0.21300554f,
    0.26601173f,
    0.21300554f, 0.10936079f, 0.03600077f, 0.00759877f, 0.00102838f};

#define SSIM_C1 0.0001f
#define SSIM_C2 0.0009f
#define INV_N (1.0f / (16.0f * 3.0f * 512.0f * 512.0f))

__device__ __forceinline__ u64 pack2(float lo, float hi) {
    u64 r;
    asm("mov.b64 %0, {%1, %2};" : "=l"(r) : "f"(lo), "f"(hi));
    return r;
}
__device__ __forceinline__ void unpack2(u64 v, float& lo, float& hi) {
    asm("mov.b64 {%0, %1}, %2;" : "=f"(lo), "=f"(hi) : "l"(v));
}
__device__ __forceinline__ u64 ffma2(u64 a, u64 b, u64 c) {
    u64 d;
    asm("fma.rn.f32x2 %0, %1, %2, %3;" : "=l"(d) : "l"(a), "l"(b), "l"(c));
    return d;
}
// broadcast a compile-time float into both f32x2 lanes (folds to a 64-bit const)
__device__ __forceinline__ u64 bcast2(float g) {
    unsigned u = __float_as_uint(g);
    return ((u64)u << 32) | (u64)u;
}

__global__ void zero_out_kernel(float* out) { out[0] = 0.0f; }

__global__ __launch_bounds__(256, 4)
void ssim_kernel(const float* __restrict__ input, const float* __restrict__ target,
                 float* __restrict__ out) {
    extern __shared__ float smem[];
    float* sHT = smem + OFF_HT;
    float* red = smem + OFF_RED;

    const int tid = threadIdx.x;
    const int plane = blockIdx.z;
    const float* Tp = target + (size_t)plane * (IMG * IMG);
    const float* Ip = input + (size_t)plane * (IMG * IMG);
    const int gx0 = blockIdx.x * TW - HALO;
    const int gy0 = blockIdx.y * TH - HALO;

    // ---- Phase 1: load tile (+halo), store interleaved pairs (t,i) and (q,r) ----
    for (int idx = tid; idx < SH * SW; idx += 256) {
        int r = idx / SW;
        int c = idx - r * SW;
        int gx = gx0 + c;
        int gy = gy0 + r;
        float t = 0.0f, v = 0.0f;
        if ((unsigned)gx < (unsigned)IMG && (unsigned)gy < (unsigned)IMG) {
            t = Tp[gy * IMG + gx];
            v = Ip[gy * IMG + gx];
        }
        int o = r * RS + c * 2;
        *(u64*)(smem + o) = pack2(t, v);
        *(u64*)(smem + PP + o) = pack2(fmaf(t, t, v * v), t * v);
    }
    __syncthreads();

    // ---- Phase 2: horizontal blur, packed. Task slots of 64 threads:
    //   ph = tid>>6 (0..3): pair = ph&1, half = ph>>1;  row = tid&63 (<42 active).
    // Each task blurs 16 output cols [half*16, half*16+16) of its row for one pair:
    // 13x ld.shared.v2.u64 -> 176 FFMA2 -> 16 st.shared.u64 (transposed).
    {
        const int ph = tid >> 6;
        const int row = tid & 63;
        const int pair = ph & 1;
        const int half = ph >> 1;
        if (row < SH) {
            const float* src = smem + pair * PP + row * RS + half * 32;
            u64 acc[16];
#pragma unroll
            for (int r = 0; r < 16; r++) acc[r] = 0ull;
#pragma unroll
            for (int q = 0; q < 13; q++) {
                ulonglong2 vv = *(const ulonglong2*)(src + q * 4);
#pragma unroll
                for (int e = 0; e < 2; e++) {
                    int j = 2 * q + e;
                    u64 v = e ? vv.y : vv.x;
#pragma unroll
                    for (int r = 0; r < 16; r++) {
                        if (j - r >= 0 && j - r < 11)
                            acc[r] = ffma2(v, bcast2(GW[j - r]), acc[r]);
                    }
                }
            }
            float* dstp = sHT + pair * PT + (half * 16) * CS + row * 2;
#pragma unroll
            for (int r = 0; r < 16; r++) *(u64*)(dstp + r * CS) = acc[r];
        }
    }
    __syncthreads();

    // ---- Phase 3: vertical blur (4 output rows/thread), packed pairs + SSIM ----
    const int tx = tid & 31;
    const int ty = tid >> 5;
    float st[2][2][4];  // [pair][lane][row]
#pragma unroll
    for (int p = 0; p < 2; p++) {
        const float* base = sHT + p * PT + tx * CS + ty * 8;
        u64 f[14];
#pragma unroll
        for (int q = 0; q < 7; q++) {
            ulonglong2 vv = *(const ulonglong2*)(base + q * 4);
            f[2 * q] = vv.x;
            f[2 * q + 1] = vv.y;
        }
#pragma unroll
        for (int r = 0; r < 4; r++) {
            u64 a = 0ull;
#pragma unroll
            for (int k = 0; k < 11; k++) a = ffma2(f[r + k], bcast2(GW[k]), a);
            unpack2(a, st[p][0][r], st[p][1][r]);
        }
    }

    float acc = 0.0f;
#pragma unroll
    for (int r = 0; r < 4; r++) {
        float mu1 = st[0][0][r], mu2 = st[0][1][r];
        float eq = st[1][0][r], e12 = st[1][1][r];
        float mu1s = mu1 * mu1;
        float mu2s = mu2 * mu2;
        float mu12 = mu1 * mu2;
        float musum = mu1s + mu2s;
        float ssum = eq - musum;  // sigma1^2 + sigma2^2
        float s12 = e12 - mu12;
        float num = (2.0f * mu12 + SSIM_C1) * (2.0f * s12 + SSIM_C2);
        float den = (musum + SSIM_C1) * (ssum + SSIM_C2);
        float ssim = __fdividef(num, den);
        float tc = smem[(HALO + ty * 4 + r) * RS + (HALO + tx) * 2];  // t lane
        acc += (tc > 0.0f) ? (1.0f - ssim) : 0.0f;
    }

#pragma unroll
    for (int off = 16; off; off >>= 1) acc += __shfl_xor_sync(0xFFFFFFFFu, acc, off);
    if (tx == 0) red[ty] = acc;
    __syncthreads();
    if (tid == 0) {
        float s = 0.0f;
#pragma unroll
        for (int w = 0; w < 8; w++) s += red[w];
        atomicAdd(out, s * INV_N);
    }
}

extern "C" void kernel_launch(void* const* d_in, const int* in_sizes, int n_in,
                              void* d_out, int out_size) {
    const float* input = (const float*)d_in[0];
    const float* target = (const float*)d_in[1];
    float* out = (float*)d_out;

    cudaFuncSetAttribute(ssim_kernel, cudaFuncAttributeMaxDynamicSharedMemorySize, SMEM_BYTES);

    zero_out_kernel<<<1, 1>>>(out);
    dim3 grid(IMG / TW, IMG / TH, NPLANES);
    ssim_kernel<<<grid, 256, SMEM_BYTES>>>(input, target, out);
}

// round 5
// speedup vs baseline: 1.4157x; 1.0522x over previous
#include <cuda_runtime.h>

// SSIM loss: depthwise 11x11 gaussian (separable) + pointwise SSIM + global mean.
// B=16, C=3, H=W=512. Planes = 48. Tile 32x32 per block, halo 5 each side.
//
// Round 5: smem 54.5KB -> 39.1KB (store only (t,i); phase-2 pair-1 tasks compute
// (t^2+i^2, t*i) on the fly) -> 5 blocks/SM. Phase 2 re-chunked to 252 active
// threads (pair x row x 11-col chunk, uniform W=11 with overlapped last chunk).
// FFMA2 (fp32x2) throughout.

typedef unsigned long long u64;

#define TW 32
#define TH 32
#define HALO 5
#define SH 42
#define SW 42
#define IMG 512
#define NPLANES 48

#define RS 92            // (t,i) pair-plane row stride in floats (46 pairs)
#define PP 3864          // SH * RS
#define CS 92            // sHT column stride in floats (46 row-pairs)
#define PT 2944          // 32 * CS, per-pair sHT plane

#define OFF_HT PP                  // 3864
#define OFF_RED (OFF_HT + 2 * PT)  // 9752
#define SMEM_FLOATS (OFF_RED + 8)
#define SMEM_BYTES (SMEM_FLOATS * 4)   // 39040 B -> 5 blocks/SM

__device__ constexpr float GW[11] = {
    0.00102838f, 0.00759877f, 0.03600077f, 0.10936079f, 0.21300554f,
    0.26601173f,
    0.21300554f, 0.10936079f, 0.03600077f, 0.00759877f, 0.00102838f};

#define SSIM_C1 0.0001f
#define SSIM_C2 0.0009f
#define INV_N (1.0f / (16.0f * 3.0f * 512.0f * 512.0f))

__device__ __forceinline__ u64 pack2(float lo, float hi) {
    u64 r;
    asm("mov.b64 %0, {%1, %2};" : "=l"(r) : "f"(lo), "f"(hi));
    return r;
}
__device__ __forceinline__ void unpack2(u64 v, float& lo, float& hi) {
    asm("mov.b64 {%0, %1}, %2;" : "=f"(lo), "=f"(hi) : "l"(v));
}
__device__ __forceinline__ u64 ffma2(u64 a, u64 b, u64 c) {
    u64 d;
    asm("fma.rn.f32x2 %0, %1, %2, %3;" : "=l"(d) : "l"(a), "l"(b), "l"(c));
    return d;
}
__device__ __forceinline__ u64 bcast2(float g) {
    unsigned u = __float_as_uint(g);
    return ((u64)u << 32) | (u64)u;
}

// Horizontal sliding blur of 11 output cols starting at c0 of one row.
// IS_PROD=false: blur the raw (t,i) pair.  IS_PROD=true: blur (t^2+i^2, t*i).
template <bool IS_PROD>
__device__ __forceinline__ void h_blur_task(const float* __restrict__ rowBase,
                                            float* __restrict__ dstBase, int c0, int row) {
    u64 acc[11];
#pragma unroll
    for (int r = 0; r < 11; r++) acc[r] = 0ull;
#pragma unroll
    for (int j = 0; j < 21; j++) {
        u64 v = *(const u64*)(rowBase + (c0 + j) * 2);
        if (IS_PROD) {
            float t, i;
            unpack2(v, t, i);
            v = pack2(fmaf(t, t, i * i), t * i);
        }
#pragma unroll
        for (int r = 0; r < 11; r++) {
            if (j - r >= 0 && j - r < 11) acc[r] = ffma2(v, bcast2(GW[j - r]), acc[r]);
        }
    }
#pragma unroll
    for (int r = 0; r < 11; r++) *(u64*)(dstBase + (c0 + r) * CS + row * 2) = acc[r];
}

__global__ void zero_out_kernel(float* out) { out[0] = 0.0f; }

__global__ __launch_bounds__(256, 5)
void ssim_kernel(const float* __restrict__ input, const float* __restrict__ target,
                 float* __restrict__ out) {
    extern __shared__ float smem[];
    float* sHT = smem + OFF_HT;
    float* red = smem + OFF_RED;

    const int tid = threadIdx.x;
    const int plane = blockIdx.z;
    const float* Tp = target + (size_t)plane * (IMG * IMG);
    const float* Ip = input + (size_t)plane * (IMG * IMG);
    const int gx0 = blockIdx.x * TW - HALO;
    const int gy0 = blockIdx.y * TH - HALO;

    // ---- Phase 1: load tile (+halo), store interleaved (t,i) pairs only ----
    for (int idx = tid; idx < SH * SW; idx += 256) {
        int r = idx / SW;
        int c = idx - r * SW;
        int gx = gx0 + c;
        int gy = gy0 + r;
        float t = 0.0f, v = 0.0f;
        if ((unsigned)gx < (unsigned)IMG && (unsigned)gy < (unsigned)IMG) {
            t = Tp[gy * IMG + gx];
            v = Ip[gy * IMG + gx];
        }
        *(u64*)(smem + r * RS + c * 2) = pack2(t, v);
    }
    __syncthreads();

    // ---- Phase 2: horizontal blur. 252 tasks = 2 pairs x 42 rows x 3 chunks.
    // task = tid; row = task % 42; g = task / 42 (0..5): pair = g/3, chunk = g%3.
    // chunk col starts {0, 11, 21} (chunk 2 overlaps col 21; duplicate write, same value).
    if (tid < 252) {
        const int row = tid % 42;
        const int g = tid / 42;
        const int chunk = (g >= 3) ? (g - 3) : g;
        const int c0 = (chunk == 2) ? 21 : chunk * 11;
        const float* rowBase = smem + row * RS;
        if (g < 3) {
            h_blur_task<false>(rowBase, sHT, c0, row);
        } else {
            h_blur_task<true>(rowBase, sHT + PT, c0, row);
        }
    }
    __syncthreads();

    // ---- Phase 3: vertical blur (4 output rows/thread), packed pairs + SSIM ----
    const int tx = tid & 31;
    const int ty = tid >> 5;
    float st[2][2][4];  // [pair][lane][row]
#pragma unroll
    for (int p = 0; p < 2; p++) {
        const float* base = sHT + p * PT + tx * CS + ty * 8;
        u64 f[14];
#pragma unroll
        for (int q = 0; q < 7; q++) {
            ulonglong2 vv = *(const ulonglong2*)(base + q * 4);
            f[2 * q] = vv.x;
            f[2 * q + 1] = vv.y;
        }
#pragma unroll
        for (int r = 0; r < 4; r++) {
            u64 a = 0ull;
#pragma unroll
            for (int k = 0; k < 11; k++) a = ffma2(f[r + k], bcast2(GW[k]), a);
            unpack2(a, st[p][0][r], st[p][1][r]);
        }
    }

    float acc = 0.0f;
#pragma unroll
    for (int r = 0; r < 4; r++) {
        float mu1 = st[0][0][r], mu2 = st[0][1][r];
        float eq = st[1][0][r], e12 = st[1][1][r];
        float mu1s = mu1 * mu1;
        float mu2s = mu2 * mu2;
        float mu12 = mu1 * mu2;
        float musum = mu1s + mu2s;
        float ssum = eq - musum;  // sigma1^2 + sigma2^2
        float s12 = e12 - mu12;
        float num = (2.0f * mu12 + SSIM_C1) * (2.0f * s12 + SSIM_C2);
        float den = (musum + SSIM_C1) * (ssum + SSIM_C2);
        float ssim = __fdividef(num, den);
        float tc = smem[(HALO + ty * 4 + r) * RS + (HALO + tx) * 2];  // t lane
        acc += (tc > 0.0f) ? (1.0f - ssim) : 0.0f;
    }

#pragma unroll
    for (int off = 16; off; off >>= 1) acc += __shfl_xor_sync(0xFFFFFFFFu, acc, off);
    if (tx == 0) red[ty] = acc;
    __syncthreads();
    if (tid == 0) {
        float s = 0.0f;
#pragma unroll
        for (int w = 0; w < 8; w++) s += red[w];
        atomicAdd(out, s * INV_N);
    }
}

extern "C" void kernel_launch(void* const* d_in, const int* in_sizes, int n_in,
                              void* d_out, int out_size) {
    const float* input = (const float*)d_in[0];
    const float* target = (const float*)d_in[1];
    float* out = (float*)d_out;

    cudaFuncSetAttribute(ssim_kernel, cudaFuncAttributeMaxDynamicSharedMemorySize, SMEM_BYTES);

    zero_out_kernel<<<1, 1>>>(out);
    dim3 grid(IMG / TW, IMG / TH, NPLANES);
    ssim_kernel<<<grid, 256, SMEM_BYTES>>>(input, target, out);
}

// round 6
// speedup vs baseline: 1.5354x; 1.0845x over previous
#include <cuda_runtime.h>

// SSIM loss: depthwise 11x11 gaussian (separable) + pointwise SSIM + global mean.
// B=16, C=3, H=W=512. Planes = 48. Tile 32x32 per block, halo 5 each side.
//
// Round 6: L1 conflict fixes. RS=90 makes phase-2 LDS.64 bank-conflict-free
// (26*lane mod 32 has period 16); warp-uniform phase-2 task map (warps 0-5 own
// one (pair,chunk) each, warps 6-7 sweep row tails) removes div/mod and
// mixed-chunk conflicts; phase-3 mask read via conflict-free LDS.64.

typedef unsigned long long u64;

#define TW 32
#define TH 32
#define HALO 5
#define SH 42
#define SW 42
#define IMG 512
#define NPLANES 48

#define RS 90            // (t,i) pair-plane row stride in floats (45 pairs): 26*l mod 32 period 16 -> LDS.64 conflict-free
#define PP 3780          // SH * RS
#define CS 92            // sHT column stride in floats: 28*l mod 32 distinct mult-of-4 -> LDS.128 conflict-free
#define PT 2944          // 32 * CS, per-pair sHT plane

#define OFF_HT PP
#define OFF_RED (OFF_HT + 2 * PT)
#define SMEM_FLOATS (OFF_RED + 8)
#define SMEM_BYTES (SMEM_FLOATS * 4)   // ~38.7 KB -> 5 blocks/SM

__device__ constexpr float GW[11] = {
    0.00102838f, 0.00759877f, 0.03600077f, 0.10936079f, 0.21300554f,
    0.26601173f,
    0.21300554f, 0.10936079f, 0.03600077f, 0.00759877f, 0.00102838f};

#define SSIM_C1 0.0001f
#define SSIM_C2 0.0009f
#define INV_N (1.0f / (16.0f * 3.0f * 512.0f * 512.0f))

__device__ __forceinline__ u64 pack2(float lo, float hi) {
    u64 r;
    asm("mov.b64 %0, {%1, %2};" : "=l"(r) : "f"(lo), "f"(hi));
    return r;
}
__device__ __forceinline__ void unpack2(u64 v, float& lo, float& hi) {
    asm("mov.b64 {%0, %1}, %2;" : "=f"(lo), "=f"(hi) : "l"(v));
}
__device__ __forceinline__ u64 ffma2(u64 a, u64 b, u64 c) {
    u64 d;
    asm("fma.rn.f32x2 %0, %1, %2, %3;" : "=l"(d) : "l"(a), "l"(b), "l"(c));
    return d;
}
__device__ __forceinline__ u64 bcast2(float g) {
    unsigned u = __float_as_uint(g);
    return ((u64)u << 32) | (u64)u;
}

// Horizontal sliding blur of 11 output cols starting at c0 of one row.
// IS_PROD=false: blur raw (t,i).  IS_PROD=true: blur (t^2+i^2, t*i) on the fly.
template <bool IS_PROD>
__device__ __forceinline__ void h_blur_task(const float* __restrict__ rowBase,
                                            float* __restrict__ dstBase, int c0, int row) {
    u64 acc[11];
#pragma unroll
    for (int r = 0; r < 11; r++) acc[r] = 0ull;
#pragma unroll
    for (int j = 0; j < 21; j++) {
        u64 v = *(const u64*)(rowBase + (c0 + j) * 2);
        if (IS_PROD) {
            float t, i;
            unpack2(v, t, i);
            v = pack2(fmaf(t, t, i * i), t * i);
        }
#pragma unroll
        for (int r = 0; r < 11; r++) {
            if (j - r >= 0 && j - r < 11) acc[r] = ffma2(v, bcast2(GW[j - r]), acc[r]);
        }
    }
#pragma unroll
    for (int r = 0; r < 11; r++) *(u64*)(dstBase + (c0 + r) * CS + row * 2) = acc[r];
}

__global__ void zero_out_kernel(float* out) { out[0] = 0.0f; }

__global__ __launch_bounds__(256, 5)
void ssim_kernel(const float* __restrict__ input, const float* __restrict__ target,
                 float* __restrict__ out) {
    extern __shared__ float smem[];
    float* sHT = smem + OFF_HT;
    float* red = smem + OFF_RED;

    const int tid = threadIdx.x;
    const int plane = blockIdx.z;
    const float* Tp = target + (size_t)plane * (IMG * IMG);
    const float* Ip = input + (size_t)plane * (IMG * IMG);
    const int gx0 = blockIdx.x * TW - HALO;
    const int gy0 = blockIdx.y * TH - HALO;

    // ---- Phase 1: load tile (+halo), store interleaved (t,i) pairs ----
    for (int idx = tid; idx < SH * SW; idx += 256) {
        int r = idx / SW;
        int c = idx - r * SW;
        int gx = gx0 + c;
        int gy = gy0 + r;
        float t = 0.0f, v = 0.0f;
        if ((unsigned)gx < (unsigned)IMG && (unsigned)gy < (unsigned)IMG) {
            t = Tp[gy * IMG + gx];
            v = Ip[gy * IMG + gx];
        }
        *(u64*)(smem + r * RS + c * 2) = pack2(t, v);
    }
    __syncthreads();

    // ---- Phase 2: horizontal blur, warp-uniform tasks.
    // Warps 0-5: warp w -> pair = (w>=3), chunk cw = w-3*pair, rows = lane (0..31).
    // Warps 6 (pair 0) / 7 (pair 1): lane = seg*10 + rr, seg=0..2, rows 32..41.
    {
        const int w = tid >> 5;
        const int lane = tid & 31;
        int pair, c0, row;
        bool active;
        if (w < 6) {
            pair = (w >= 3) ? 1 : 0;
            int cw = w - 3 * pair;
            c0 = (cw == 2) ? 21 : cw * 11;
            row = lane;
            active = true;
        } else {
            pair = w - 6;
            int seg = (lane >= 20) ? 2 : (lane >= 10 ? 1 : 0);
            c0 = (seg == 2) ? 21 : seg * 11;
            row = 32 + lane - seg * 10;
            active = (lane < 30);
        }
        if (active) {
            const float* rowBase = smem + row * RS;
            if (pair == 0)
                h_blur_task<false>(rowBase, sHT, c0, row);
            else
                h_blur_task<true>(rowBase, sHT + PT, c0, row);
        }
    }
    __syncthreads();

    // ---- Phase 3: vertical blur (4 output rows/thread), packed pairs + SSIM ----
    const int tx = tid & 31;
    const int ty = tid >> 5;
    float st[2][2][4];  // [pair][lane][row]
#pragma unroll
    for (int p = 0; p < 2; p++) {
        const float* base = sHT + p * PT + tx * CS + ty * 8;
        u64 f[14];
#pragma unroll
        for (int q = 0; q < 7; q++) {
            ulonglong2 vv = *(const ulonglong2*)(base + q * 4);
            f[2 * q] = vv.x;
            f[2 * q + 1] = vv.y;
        }
#pragma unroll
        for (int r = 0; r < 4; r++) {
            u64 a = 0ull;
#pragma unroll
            for (int k = 0; k < 11; k++) a = ffma2(f[r + k], bcast2(GW[k]), a);
            unpack2(a, st[p][0][r], st[p][1][r]);
        }
    }

    float acc = 0.0f;
#pragma unroll
    for (int r = 0; r < 4; r++) {
        float mu1 = st[0][0][r], mu2 = st[0][1][r];
        float eq = st[1][0][r], e12 = st[1][1][r];
        float mu1s = mu1 * mu1;
        float mu2s = mu2 * mu2;
        float mu12 = mu1 * mu2;
        float musum = mu1s + mu2s;
        float ssum = eq - musum;  // sigma1^2 + sigma2^2
        float s12 = e12 - mu12;
        float num = (2.0f * mu12 + SSIM_C1) * (2.0f * s12 + SSIM_C2);
        float den = (musum + SSIM_C1) * (ssum + SSIM_C2);
        float ssim = __fdividef(num, den);
        // mask: load (t,i) pair via conflict-free LDS.64, use t lane
        u64 tv = *(const u64*)(smem + (HALO + ty * 4 + r) * RS + (HALO + tx) * 2);
        float tc, ic;
        unpack2(tv, tc, ic);
        acc += (tc > 0.0f) ? (1.0f - ssim) : 0.0f;
    }

#pragma unroll
    for (int off = 16; off; off >>= 1) acc += __shfl_xor_sync(0xFFFFFFFFu, acc, off);
    if (tx == 0) red[ty] = acc;
    __syncthreads();
    if (tid == 0) {
        float s = 0.0f;
#pragma unroll
        for (int w = 0; w < 8; w++) s += red[w];
        atomicAdd(out, s * INV_N);
    }
}

extern "C" void kernel_launch(void* const* d_in, const int* in_sizes, int n_in,
                              void* d_out, int out_size) {
    const float* input = (const float*)d_in[0];
    const float* target = (const float*)d_in[1];
    float* out = (float*)d_out;

    cudaFuncSetAttribute(ssim_kernel, cudaFuncAttributeMaxDynamicSharedMemorySize, SMEM_BYTES);

    zero_out_kernel<<<1, 1>>>(out);
    dim3 grid(IMG / TW, IMG / TH, NPLANES);
    ssim_kernel<<<grid, 256, SMEM_BYTES>>>(input, target, out);
}

// round 7
// speedup vs baseline: 1.5843x; 1.0319x over previous
#include <cuda_runtime.h>

// SSIM loss: depthwise 11x11 gaussian (separable) + pointwise SSIM + global mean.
// B=16, C=3, H=W=512. Planes = 48. Tile 32x32 per block, halo 5 each side.
//
// Round 7: phase-3 redundancy cut. 128 threads x 8 output rows (was 256 x 4):
// per-pair 9x LDS.128 streamed into 8 sliding u64 accumulators (register-lean,
// keeps occ 5). P3 load wavefronts 448 -> 288. P2 prod tasks load float2 and
// pack once (ALU trim). Everything else as round 6.

typedef unsigned long long u64;

#define TW 32
#define TH 32
#define HALO 5
#define SH 42
#define SW 42
#define IMG 512
#define NPLANES 48

#define RS 90            // (t,i) pair-plane row stride in floats: 13*l mod 32 distinct -> LDS.64 conflict-free
#define PP 3780          // SH * RS
#define CS 92            // sHT column stride in floats: quad 7*tx mod 8 distinct -> LDS.128 conflict-free
#define PT 2944          // 32 * CS, per-pair sHT plane

#define OFF_HT PP
#define OFF_RED (OFF_HT + 2 * PT)
#define SMEM_FLOATS (OFF_RED + 8)
#define SMEM_BYTES (SMEM_FLOATS * 4)   // ~38.7 KB -> 5 blocks/SM

__device__ constexpr float GW[11] = {
    0.00102838f, 0.00759877f, 0.03600077f, 0.10936079f, 0.21300554f,
    0.26601173f,
    0.21300554f, 0.10936079f, 0.03600077f, 0.00759877f, 0.00102838f};

#define SSIM_C1 0.0001f
#define SSIM_C2 0.0009f
#define INV_N (1.0f / (16.0f * 3.0f * 512.0f * 512.0f))

__device__ __forceinline__ u64 pack2(float lo, float hi) {
    u64 r;
    asm("mov.b64 %0, {%1, %2};" : "=l"(r) : "f"(lo), "f"(hi));
    return r;
}
__device__ __forceinline__ void unpack2(u64 v, float& lo, float& hi) {
    asm("mov.b64 {%0, %1}, %2;" : "=f"(lo), "=f"(hi) : "l"(v));
}
__device__ __forceinline__ u64 ffma2(u64 a, u64 b, u64 c) {
    u64 d;
    asm("fma.rn.f32x2 %0, %1, %2, %3;" : "=l"(d) : "l"(a), "l"(b), "l"(c));
    return d;
}
__device__ __forceinline__ u64 bcast2(float g) {
    unsigned u = __float_as_uint(g);
    return ((u64)u << 32) | (u64)u;
}

// Horizontal sliding blur of 11 output cols starting at c0 of one row.
// IS_PROD=false: blur raw (t,i).  IS_PROD=true: blur (t^2+i^2, t*i) on the fly.
template <bool IS_PROD>
__device__ __forceinline__ void h_blur_task(const float* __restrict__ rowBase,
                                            float* __restrict__ dstBase, int c0, int row) {
    u64 acc[11];
#pragma unroll
    for (int r = 0; r < 11; r++) acc[r] = 0ull;
#pragma unroll
    for (int j = 0; j < 21; j++) {
        u64 v;
        if (IS_PROD) {
            float2 ti = *(const float2*)(rowBase + (c0 + j) * 2);
            v = pack2(fmaf(ti.x, ti.x, ti.y * ti.y), ti.x * ti.y);
        } else {
            v = *(const u64*)(rowBase + (c0 + j) * 2);
        }
#pragma unroll
        for (int r = 0; r < 11; r++) {
            if (j - r >= 0 && j - r < 11) acc[r] = ffma2(v, bcast2(GW[j - r]), acc[r]);
        }
    }
#pragma unroll
    for (int r = 0; r < 11; r++) *(u64*)(dstBase + (c0 + r) * CS + row * 2) = acc[r];
}

// Streaming vertical blur: 8 outputs from 18 consecutive row values of one column,
// loaded as 9 ulonglong2 and consumed immediately (keeps <= ~24 live regs).
__device__ __forceinline__ void v_blur8(const float* __restrict__ base, u64 (&acc)[8]) {
#pragma unroll
    for (int r = 0; r < 8; r++) acc[r] = 0ull;
#pragma unroll
    for (int q = 0; q < 9; q++) {
        ulonglong2 vv = *(const ulonglong2*)(base + q * 4);
#pragma unroll
        for (int e = 0; e < 2; e++) {
            const int j = 2 * q + e;
            u64 v = e ? vv.y : vv.x;
#pragma unroll
            for (int r = 0; r < 8; r++) {
                if (j - r >= 0 && j - r < 11) acc[r] = ffma2(v, bcast2(GW[j - r]), acc[r]);
            }
        }
    }
}

__global__ void zero_out_kernel(float* out) { out[0] = 0.0f; }

__global__ __launch_bounds__(256, 5)
void ssim_kernel(const float* __restrict__ input, const float* __restrict__ target,
                 float* __restrict__ out) {
    extern __shared__ float smem[];
    float* sHT = smem + OFF_HT;
    float* red = smem + OFF_RED;

    const int tid = threadIdx.x;
    const int plane = blockIdx.z;
    const float* Tp = target + (size_t)plane * (IMG * IMG);
    const float* Ip = input + (size_t)plane * (IMG * IMG);
    const int gx0 = blockIdx.x * TW - HALO;
    const int gy0 = blockIdx.y * TH - HALO;

    // ---- Phase 1: load tile (+halo), store interleaved (t,i) pairs ----
    for (int idx = tid; idx < SH * SW; idx += 256) {
        int r = idx / SW;
        int c = idx - r * SW;
        int gx = gx0 + c;
        int gy = gy0 + r;
        float t = 0.0f, v = 0.0f;
        if ((unsigned)gx < (unsigned)IMG && (unsigned)gy < (unsigned)IMG) {
            t = Tp[gy * IMG + gx];
            v = Ip[gy * IMG + gx];
        }
        *(u64*)(smem + r * RS + c * 2) = pack2(t, v);
    }
    __syncthreads();

    // ---- Phase 2: horizontal blur, warp-uniform tasks (round-6 layout).
    // Warps 0-5: warp w -> pair = (w>=3), chunk cw = w-3*pair, rows = lane.
    // Warps 6 (pair 0) / 7 (pair 1): lane = seg*10 + rr, rows 32..41.
    {
        const int w = tid >> 5;
        const int lane = tid & 31;
        int pair, c0, row;
        bool active;
        if (w < 6) {
            pair = (w >= 3) ? 1 : 0;
            int cw = w - 3 * pair;
            c0 = (cw == 2) ? 21 : cw * 11;
            row = lane;
            active = true;
        } else {
            pair = w - 6;
            int seg = (lane >= 20) ? 2 : (lane >= 10 ? 1 : 0);
            c0 = (seg == 2) ? 21 : seg * 11;
            row = 32 + lane - seg * 10;
            active = (lane < 30);
        }
        if (active) {
            const float* rowBase = smem + row * RS;
            if (pair == 0)
                h_blur_task<false>(rowBase, sHT, c0, row);
            else
                h_blur_task<true>(rowBase, sHT + PT, c0, row);
        }
    }
    __syncthreads();

    // ---- Phase 3: vertical blur + SSIM. 128 threads: (tx = col, tg = 8-row group).
    float acc = 0.0f;
    if (tid < 128) {
        const int tx = tid & 31;
        const int tg = tid >> 5;  // 0..3, output rows [8*tg, 8*tg+8)

        u64 mu[8];
        v_blur8(sHT + tx * CS + tg * 16, mu);        // pair 0 -> (mu1, mu2)
        u64 pr[8];
        v_blur8(sHT + PT + tx * CS + tg * 16, pr);   // pair 1 -> (Eq, E12)

#pragma unroll
        for (int r = 0; r < 8; r++) {
            float mu1, mu2, eq, e12;
            unpack2(mu[r], mu1, mu2);
            unpack2(pr[r], eq, e12);
            float mu1s = mu1 * mu1;
            float mu2s = mu2 * mu2;
            float mu12 = mu1 * mu2;
            float musum = mu1s + mu2s;
            float ssum = eq - musum;   // sigma1^2 + sigma2^2
            float s12 = e12 - mu12;
            float num = (2.0f * mu12 + SSIM_C1) * (2.0f * s12 + SSIM_C2);
            float den = (musum + SSIM_C1) * (ssum + SSIM_C2);
            float ssim = __fdividef(num, den);
            // mask: conflict-free LDS.64 of the (t,i) pair; use t lane
            u64 tv = *(const u64*)(smem + (HALO + tg * 8 + r) * RS + (HALO + tx) * 2);
            float tc, ic;
            unpack2(tv, tc, ic);
            acc += (tc > 0.0f) ? (1.0f - ssim) : 0.0f;
        }

#pragma unroll
        for (int off = 16; off; off >>= 1) acc += __shfl_xor_sync(0xFFFFFFFFu, acc, off);
        if (tx == 0) red[tg] = acc;
    }
    __syncthreads();
    if (tid == 0) {
        float s = 0.0f;
#pragma unroll
        for (int w = 0; w < 4; w++) s += red[w];
        atomicAdd(out, s * INV_N);
    }
}

extern "C" void kernel_launch(void* const* d_in, const int* in_sizes, int n_in,
                              void* d_out, int out_size) {
    const float* input = (const float*)d_in[0];
    const float* target = (const float*)d_in[1];
    float* out = (float*)d_out;

    cudaFuncSetAttribute(ssim_kernel, cudaFuncAttributeMaxDynamicSharedMemorySize, SMEM_BYTES);

    zero_out_kernel<<<1, 1>>>(out);
    dim3 grid(IMG / TW, IMG / TH, NPLANES);
    ssim_kernel<<<grid, 256, SMEM_BYTES>>>(input, target, out);
}

// round 8
// speedup vs baseline: 1.5934x; 1.0057x over previous
#include <cuda_runtime.h>

// SSIM loss: depthwise 11x11 gaussian (separable) + pointwise SSIM + global mean.
// B=16, C=3, H=W=512. Planes = 48. Tile 32x32 per block, halo 5 each side.
//
// Round 8: all-warp phase 3 (256 threads, one (pair,col,8rows) vertical blur each;
// pair-1 publishes via conflict-free smem exchange in the dead pair-1 plane),
// CS 92->84 (still conflict-free, smem 35.8KB), __launch_bounds__(256,6) for
// 6 blocks/SM (42-reg target). FFMA2 packing throughout.

typedef unsigned long long u64;

#define TW 32
#define TH 32
#define HALO 5
#define SH 42
#define SW 42
#define IMG 512
#define NPLANES 48

#define RS 90            // (t,i) pair-plane row stride (floats): LDS.64 conflict-free
#define PP 3780          // SH * RS
#define CS 84            // sHT column stride (floats): quad 5*tx mod 8 distinct -> LDS.128 conflict-free
#define PT 2688          // 32 * CS, per-pair sHT plane

#define OFF_HT PP
#define OFF_RED (OFF_HT + 2 * PT)
#define SMEM_FLOATS (OFF_RED + 8)
#define SMEM_BYTES (SMEM_FLOATS * 4)   // 36656 B -> 6 blocks/SM

__device__ constexpr float GW[11] = {
    0.00102838f, 0.00759877f, 0.03600077f, 0.10936079f, 0.21300554f,
    0.26601173f,
    0.21300554f, 0.10936079f, 0.03600077f, 0.00759877f, 0.00102838f};

#define SSIM_C1 0.0001f
#define SSIM_C2 0.0009f
#define INV_N (1.0f / (16.0f * 3.0f * 512.0f * 512.0f))

__device__ __forceinline__ u64 pack2(float lo, float hi) {
    u64 r;
    asm("mov.b64 %0, {%1, %2};" : "=l"(r) : "f"(lo), "f"(hi));
    return r;
}
__device__ __forceinline__ void unpack2(u64 v, float& lo, float& hi) {
    asm("mov.b64 {%0, %1}, %2;" : "=f"(lo), "=f"(hi) : "l"(v));
}
__device__ __forceinline__ u64 ffma2(u64 a, u64 b, u64 c) {
    u64 d;
    asm("fma.rn.f32x2 %0, %1, %2, %3;" : "=l"(d) : "l"(a), "l"(b), "l"(c));
    return d;
}
__device__ __forceinline__ u64 bcast2(float g) {
    unsigned u = __float_as_uint(g);
    return ((u64)u << 32) | (u64)u;
}

// Horizontal sliding blur of 11 output cols starting at c0 of one row.
template <bool IS_PROD>
__device__ __forceinline__ void h_blur_task(const float* __restrict__ rowBase,
                                            float* __restrict__ dstBase, int c0, int row) {
    u64 acc[11];
#pragma unroll
    for (int r = 0; r < 11; r++) acc[r] = 0ull;
#pragma unroll
    for (int j = 0; j < 21; j++) {
        u64 v;
        if (IS_PROD) {
            float2 ti = *(const float2*)(rowBase + (c0 + j) * 2);
            v = pack2(fmaf(ti.x, ti.x, ti.y * ti.y), ti.x * ti.y);
        } else {
            v = *(const u64*)(rowBase + (c0 + j) * 2);
        }
#pragma unroll
        for (int r = 0; r < 11; r++) {
            if (j - r >= 0 && j - r < 11) acc[r] = ffma2(v, bcast2(GW[j - r]), acc[r]);
        }
    }
#pragma unroll
    for (int r = 0; r < 11; r++) *(u64*)(dstBase + (c0 + r) * CS + row * 2) = acc[r];
}

// Streaming vertical blur: 8 outputs from 18 consecutive row values of one column.
__device__ __forceinline__ void v_blur8(const float* __restrict__ base, u64 (&acc)[8]) {
#pragma unroll
    for (int r = 0; r < 8; r++) acc[r] = 0ull;
#pragma unroll
    for (int q = 0; q < 9; q++) {
        ulonglong2 vv = *(const ulonglong2*)(base + q * 4);
#pragma unroll
        for (int e = 0; e < 2; e++) {
            const int j = 2 * q + e;
            u64 v = e ? vv.y : vv.x;
#pragma unroll
            for (int r = 0; r < 8; r++) {
                if (j - r >= 0 && j - r < 11) acc[r] = ffma2(v, bcast2(GW[j - r]), acc[r]);
            }
        }
    }
}

__global__ void zero_out_kernel(float* out) { out[0] = 0.0f; }

__global__ __launch_bounds__(256, 6)
void ssim_kernel(const float* __restrict__ input, const float* __restrict__ target,
                 float* __restrict__ out) {
    extern __shared__ float smem[];
    float* sHT = smem + OFF_HT;
    float* red = smem + OFF_RED;

    const int tid = threadIdx.x;
    const int plane = blockIdx.z;
    const float* Tp = target + (size_t)plane * (IMG * IMG);
    const float* Ip = input + (size_t)plane * (IMG * IMG);
    const int gx0 = blockIdx.x * TW - HALO;
    const int gy0 = blockIdx.y * TH - HALO;

    // ---- Phase 1: load tile (+halo), store interleaved (t,i) pairs ----
    for (int idx = tid; idx < SH * SW; idx += 256) {
        int r = idx / SW;
        int c = idx - r * SW;
        int gx = gx0 + c;
        int gy = gy0 + r;
        float t = 0.0f, v = 0.0f;
        if ((unsigned)gx < (unsigned)IMG && (unsigned)gy < (unsigned)IMG) {
            t = Tp[gy * IMG + gx];
            v = Ip[gy * IMG + gx];
        }
        *(u64*)(smem + r * RS + c * 2) = pack2(t, v);
    }
    __syncthreads();

    // ---- Phase 2: horizontal blur, warp-uniform tasks ----
    {
        const int w = tid >> 5;
        const int lane = tid & 31;
        int pair, c0, row;
        bool active;
        if (w < 6) {
            pair = (w >= 3) ? 1 : 0;
            int cw = w - 3 * pair;
            c0 = (cw == 2) ? 21 : cw * 11;
            row = lane;
            active = true;
        } else {
            pair = w - 6;
            int seg = (lane >= 20) ? 2 : (lane >= 10 ? 1 : 0);
            c0 = (seg == 2) ? 21 : seg * 11;
            row = 32 + lane - seg * 10;
            active = (lane < 30);
        }
        if (active) {
            const float* rowBase = smem + row * RS;
            if (pair == 0)
                h_blur_task<false>(rowBase, sHT, c0, row);
            else
                h_blur_task<true>(rowBase, sHT + PT, c0, row);
        }
    }
    __syncthreads();

    // ---- Phase 3: all-warp vertical blur. thread -> (pair, col tx, 8-row group tg).
    const int pair = tid >> 7;        // warps 0-3 -> pair 0, warps 4-7 -> pair 1
    const int tx = tid & 31;
    const int tg = (tid >> 5) & 3;    // output rows [8*tg, 8*tg+8)

    u64 res[8];
    v_blur8(sHT + pair * PT + tx * CS + tg * 16, res);
    __syncthreads();  // all sHT reads complete before pair-1 plane is overwritten

    // pair-1 threads publish results into scratch in the (dead) pair-1 plane.
    // slot stride 20 floats: 16B aligned, quad 5*tx mod 8 distinct -> conflict-free.
    if (pair == 1) {
        float* x = sHT + PT + (tx + tg * 32) * 20;
#pragma unroll
        for (int q = 0; q < 4; q++) {
            ulonglong2 vv;
            vv.x = res[2 * q];
            vv.y = res[2 * q + 1];
            *(ulonglong2*)(x + q * 4) = vv;
        }
    }
    __syncthreads();

    if (pair == 0) {
        u64 pr[8];
        const float* x = sHT + PT + (tx + tg * 32) * 20;
#pragma unroll
        for (int q = 0; q < 4; q++) {
            ulonglong2 vv = *(const ulonglong2*)(x + q * 4);
            pr[2 * q] = vv.x;
            pr[2 * q + 1] = vv.y;
        }

        float acc = 0.0f;
#pragma unroll
        for (int r = 0; r < 8; r++) {
            float mu1, mu2, eq, e12;
            unpack2(res[r], mu1, mu2);
            unpack2(pr[r], eq, e12);
            float mu1s = mu1 * mu1;
            float mu2s = mu2 * mu2;
            float mu12 = mu1 * mu2;
            float musum = mu1s + mu2s;
            float ssum = eq - musum;   // sigma1^2 + sigma2^2
            float s12 = e12 - mu12;
            float num = (2.0f * mu12 + SSIM_C1) * (2.0f * s12 + SSIM_C2);
            float den = (musum + SSIM_C1) * (ssum + SSIM_C2);
            float ssim = __fdividef(num, den);
            u64 tv = *(const u64*)(smem + (HALO + tg * 8 + r) * RS + (HALO + tx) * 2);
            float tc, ic;
            unpack2(tv, tc, ic);
            acc += (tc > 0.0f) ? (1.0f - ssim) : 0.0f;
        }

#pragma unroll
        for (int off = 16; off; off >>= 1) acc += __shfl_xor_sync(0xFFFFFFFFu, acc, off);
        if (tx == 0) red[tg] = acc;
    }
    __syncthreads();
    if (tid == 0) {
        float s = red[0] + red[1] + red[2] + red[3];
        atomicAdd(out, s * INV_N);
    }
}

extern "C" void kernel_launch(void* const* d_in, const int* in_sizes, int n_in,
                              void* d_out, int out_size) {
    const float* input = (const float*)d_in[0];
    const float* target = (const float*)d_in[1];
    float* out = (float*)d_out;

    cudaFuncSetAttribute(ssim_kernel, cudaFuncAttributeMaxDynamicSharedMemorySize, SMEM_BYTES);

    zero_out_kernel<<<1, 1>>>(out);
    dim3 grid(IMG / TW, IMG / TH, NPLANES);
    ssim_kernel<<<grid, 256, SMEM_BYTES>>>(input, target, out);
}